// round 17
// baseline (speedup 1.0000x reference)
#include <cuda_runtime.h>
#include <cuda_bf16.h>
#include <math.h>
#include <stdint.h>

#define BATCH   2
#define SEQ     2048
#define DMODEL  1024
#define HEADS   16
#define DH      64
#define NROWS   (BATCH * SEQ)            // 4096
#define ZBH     (BATCH * HEADS)          // 32
#define SCL2 0.1803368801111204f         // 0.125 * log2(e)

typedef __nv_bfloat16 bf16;

// ------------------------- device scratch (statics) -------------------------
__device__ bf16 g_q_hi[NROWS * DMODEL], g_q_lo[NROWS * DMODEL];
__device__ bf16 g_k_hi[NROWS * DMODEL], g_k_lo[NROWS * DMODEL];
__device__ bf16 g_v_hi[NROWS * DMODEL], g_v_lo[NROWS * DMODEL];

__device__ bf16 g_wqT_hi[DMODEL * DMODEL], g_wqT_lo[DMODEL * DMODEL];
__device__ bf16 g_wkT_hi[DMODEL * DMODEL], g_wkT_lo[DMODEL * DMODEL];
__device__ bf16 g_wvT_hi[DMODEL * DMODEL], g_wvT_lo[DMODEL * DMODEL];
__device__ bf16 g_woT_hi[DMODEL * DMODEL], g_woT_lo[DMODEL * DMODEL];

__device__ bf16 g_Qh_hi [ZBH * SEQ * DH], g_Qh_lo [ZBH * SEQ * DH];  // [b,h,s,d] pre-scaled SCL2
__device__ bf16 g_Kh_hi [ZBH * SEQ * DH], g_Kh_lo [ZBH * SEQ * DH];  // [b,h,s,d]
__device__ bf16 g_VhT_hi[ZBH * DH * SEQ], g_VhT_lo[ZBH * DH * SEQ];  // [b,h,d,s]

__device__ bf16 g_Att_hi[NROWS * DMODEL], g_Att_lo[NROWS * DMODEL];  // [b,s,h*d]

// ------------------------------- helpers ------------------------------------
__device__ __forceinline__ void split1(float x, bf16& h, bf16& l) {
    h = __float2bfloat16_rn(x);
    l = __float2bfloat16_rn(x - __bfloat162float(h));
}
__device__ __forceinline__ void split2pack(float x0, float x1, unsigned& hi, unsigned& lo) {
    bf16 h0, l0, h1, l1;
    split1(x0, h0, l0); split1(x1, h1, l1);
    __nv_bfloat162 th; th.x = h0; th.y = h1;
    __nv_bfloat162 tl; tl.x = l0; tl.y = l1;
    hi = *(unsigned*)&th; lo = *(unsigned*)&tl;
}
__device__ __forceinline__ float ex2(float x) {
    float r;
    asm("ex2.approx.ftz.f32 %0, %1;" : "=f"(r) : "f"(x));
    return r;
}
__device__ __forceinline__ void cpasync16(bf16* dst, const bf16* src) {
    uint32_t d = (uint32_t)__cvta_generic_to_shared(dst);
    asm volatile("cp.async.cg.shared.global [%0], [%1], 16;\n" :: "r"(d), "l"(src));
}
__device__ __forceinline__ void cpasync16_u(uint32_t d, const bf16* src) {
    asm volatile("cp.async.cg.shared.global [%0], [%1], 16;\n" :: "r"(d), "l"(src));
}
__device__ __forceinline__ void cp_commit() { asm volatile("cp.async.commit_group;\n"); }
template<int N> __device__ __forceinline__ void cp_wait() {
    asm volatile("cp.async.wait_group %0;\n" :: "n"(N));
}
__device__ __forceinline__ void mma16816(float* c, const unsigned* a, const unsigned* b) {
    asm volatile(
        "mma.sync.aligned.m16n8k16.row.col.f32.bf16.bf16.f32 "
        "{%0,%1,%2,%3}, {%4,%5,%6,%7}, {%8,%9}, {%0,%1,%2,%3};"
        : "+f"(c[0]), "+f"(c[1]), "+f"(c[2]), "+f"(c[3])
        : "r"(a[0]), "r"(a[1]), "r"(a[2]), "r"(a[3]), "r"(b[0]), "r"(b[1]));
}
__device__ __forceinline__ void ldm_x4(unsigned* r, uint32_t addr) {
    asm volatile("ldmatrix.sync.aligned.m8n8.x4.shared.b16 {%0,%1,%2,%3}, [%4];"
        : "=r"(r[0]), "=r"(r[1]), "=r"(r[2]), "=r"(r[3]) : "r"(addr));
}
__device__ __forceinline__ void ldm_x2(unsigned* r, uint32_t addr) {
    asm volatile("ldmatrix.sync.aligned.m8n8.x2.shared.b16 {%0,%1}, [%2];"
        : "=r"(r[0]), "=r"(r[1]) : "r"(addr));
}
// SW64 swizzle for 64B rows: XOR bits [4:6) with bits [7:9). 16B-alignment kept.
__device__ __forceinline__ uint32_t swz64(uint32_t off) {
    return off ^ ((off >> 3) & 0x30);
}

// ---------------- single prep launch: splits + weight transposes ------------
__global__ void prep_k(const float* __restrict__ q, const float* __restrict__ k,
                       const float* __restrict__ v,
                       const float* __restrict__ wq, const float* __restrict__ wk,
                       const float* __restrict__ wv, const float* __restrict__ wo,
                       bf16* qh, bf16* ql, bf16* kh, bf16* kl, bf16* vh, bf16* vl,
                       bf16* wqh, bf16* wql, bf16* wkh, bf16* wkl,
                       bf16* wvh, bf16* wvl, bf16* woh, bf16* wol)
{
    const int z = blockIdx.z;
    const int tid = threadIdx.x;
    if (z < 3) {
        const float* src = (z == 0) ? q : (z == 1) ? k : v;
        bf16* hi = (z == 0) ? qh : (z == 1) ? kh : vh;
        bf16* lo = (z == 0) ? ql : (z == 1) ? kl : vl;
        const int bid = blockIdx.y * 32 + blockIdx.x;
        const int n = NROWS * DMODEL;
        for (int i = bid * 256 + tid; i < n; i += 1024 * 256) {
            bf16 h, l; split1(src[i], h, l);
            hi[i] = h; lo[i] = l;
        }
    } else {
        const int zz = z - 3;
        const float* W = (zz == 0) ? wq : (zz == 1) ? wk : (zz == 2) ? wv : wo;
        bf16* hiT = (zz == 0) ? wqh : (zz == 1) ? wkh : (zz == 2) ? wvh : woh;
        bf16* loT = (zz == 0) ? wql : (zz == 1) ? wkl : (zz == 2) ? wvl : wol;
        __shared__ float t[32][33];
        const int tx = tid & 31, ty = tid >> 5;
        const int bn = blockIdx.x * 32;
        const int bk = blockIdx.y * 32;
        for (int r = ty; r < 32; r += 8)
            t[r][tx] = W[(size_t)(bk + r) * DMODEL + bn + tx];
        __syncthreads();
        for (int r = ty; r < 32; r += 8) {
            float val = t[tx][r];
            bf16 h, l; split1(val, h, l);
            size_t idx = (size_t)(bn + r) * DMODEL + bk + tx;
            hiT[idx] = h; loT[idx] = l;
        }
    }
}

// ---------------------------------------------------------------------------
// 3xBF16 GEMM core: 64B swizzled rows, 64KB smem, 3 CTAs/SM target.
//   Tile bytes per stage per operand: 128 rows * 64B = 8192.
//   Layout: sAh[2]@0, sAl[2]@16384, sBh[2]@32768, sBl[2]@49152. Total 65536.
//   mode 0: fp32 C; 1: bf16 hi/lo [b,h,s,d]; 2: bf16 hi/lo [b,h,d,s]
// ---------------------------------------------------------------------------
__device__ __forceinline__ void gemm3_body(
    const bf16* __restrict__ Ah, const bf16* __restrict__ Al,
    const bf16* __restrict__ Bh, const bf16* __restrict__ Bl,
    const float* __restrict__ bias, void* Cv, void* C2v, int mode, float alpha)
{
    constexpr int BM = 128, BN = 128, BK = 32;
    constexpr int STG = BM * 64;          // 8192 bytes per stage

    extern __shared__ bf16 sm[];
    const uint32_t usm = (uint32_t)__cvta_generic_to_shared(sm);

    const int tid = threadIdx.x;
    const int lane = tid & 31, wid = tid >> 5;
    const int m0 = blockIdx.y * BM;
    const int n0 = blockIdx.x * BN;
    const int wm = (wid & 1) * 64;
    const int wn = (wid >> 1) * 32;
    const int g  = lane >> 2;
    const int tk = (lane & 3) * 2;

    const int lq = lane >> 3, li = lane & 7;
    const int a_row  = (lq & 1) * 8 + li;
    const int a_colb = (lq >> 1) * 16;     // byte offset of 16B chunk
    const int b_row  = li;
    const int b_colb = (lq & 1) * 16;

    float acc[4][4][4];
#pragma unroll
    for (int mi = 0; mi < 4; mi++)
#pragma unroll
        for (int ni = 0; ni < 4; ni++)
#pragma unroll
            for (int r = 0; r < 4; r++) acc[mi][ni][r] = 0.f;

    auto stage_load = [&](int s, int kt) {
#pragma unroll
        for (int c = tid; c < BM * 4; c += 256) {
            int row = c >> 2, q = c & 3;
            uint32_t so = swz64((uint32_t)(row * 64 + q * 16));
            size_t goA = (size_t)(m0 + row) * DMODEL + kt + q * 8;
            size_t goB = (size_t)(n0 + row) * DMODEL + kt + q * 8;
            cpasync16_u(usm + (unsigned)(s * STG) + so,           Ah + goA);
            cpasync16_u(usm + 16384u + (unsigned)(s * STG) + so,  Al + goA);
            cpasync16_u(usm + 32768u + (unsigned)(s * STG) + so,  Bh + goB);
            cpasync16_u(usm + 49152u + (unsigned)(s * STG) + so,  Bl + goB);
        }
        cp_commit();
    };

    auto compute = [&](int s) {
        const uint32_t aH = usm + (unsigned)(s * STG);
        const uint32_t aL = usm + 16384u + (unsigned)(s * STG);
        const uint32_t bH = usm + 32768u + (unsigned)(s * STG);
        const uint32_t bL = usm + 49152u + (unsigned)(s * STG);
#pragma unroll
        for (int kh = 0; kh < 2; kh++) {
            const int kbb = kh * 32;       // byte offset of K-half
#pragma unroll
            for (int nih = 0; nih < 2; nih++) {
                unsigned bh[2][2], bl[2][2];
#pragma unroll
                for (int j = 0; j < 2; j++) {
                    int ni = 2 * nih + j;
                    uint32_t off = swz64((uint32_t)((wn + ni * 8 + b_row) * 64 + kbb + b_colb));
                    ldm_x2(bh[j], bH + off);
                    ldm_x2(bl[j], bL + off);
                }
#pragma unroll
                for (int mi = 0; mi < 4; mi++) {
                    unsigned ah[4], al[4];
                    uint32_t off = swz64((uint32_t)((wm + mi * 16 + a_row) * 64 + kbb + a_colb));
                    ldm_x4(ah, aH + off);
                    ldm_x4(al, aL + off);
#pragma unroll
                    for (int j = 0; j < 2; j++) {
                        int ni = 2 * nih + j;
                        mma16816(acc[mi][ni], ah, bh[j]);
                        mma16816(acc[mi][ni], ah, bl[j]);
                        mma16816(acc[mi][ni], al, bh[j]);
                    }
                }
            }
        }
    };

    constexpr int NITER = DMODEL / BK;
    stage_load(0, 0);
    for (int it = 0; it < NITER; it++) {
        if (it + 1 < NITER) { stage_load((it + 1) & 1, (it + 1) * BK); cp_wait<1>(); }
        else                { cp_wait<0>(); }
        __syncthreads();
        compute(it & 1);
        __syncthreads();
    }

#pragma unroll
    for (int mi = 0; mi < 4; mi++)
#pragma unroll
        for (int ni = 0; ni < 4; ni++)
#pragma unroll
            for (int half = 0; half < 2; half++) {
                const int r = m0 + wm + mi * 16 + g + half * 8;
                const int c = n0 + wn + ni * 8 + tk;
                float v0 = acc[mi][ni][half * 2 + 0];
                float v1 = acc[mi][ni][half * 2 + 1];
                if (bias) { v0 += bias[c]; v1 += bias[c + 1]; }
                v0 *= alpha; v1 *= alpha;

                if (mode == 0) {
                    float2 o; o.x = v0; o.y = v1;
                    *(float2*)&((float*)Cv)[(size_t)r * DMODEL + c] = o;
                } else if (mode == 1) {
                    int b = r >> 11, s = r & (SEQ - 1);
                    int h = c >> 6,  d = c & (DH - 1);
                    size_t idx = ((size_t)((b * HEADS + h) * SEQ + s)) * DH + d;
                    unsigned uh, ul; split2pack(v0, v1, uh, ul);
                    *(unsigned*)((bf16*)Cv  + idx) = uh;
                    *(unsigned*)((bf16*)C2v + idx) = ul;
                } else { // mode 2: [b,h,d,s]
                    int b = r >> 11, s = r & (SEQ - 1);
                    int h = c >> 6,  d = c & (DH - 1);
                    size_t idx = ((size_t)((b * HEADS + h) * DH + d)) * SEQ + s;
                    bf16 h0, l0, h1, l1; split1(v0, h0, l0); split1(v1, h1, l1);
                    ((bf16*)Cv)[idx]        = h0;
                    ((bf16*)Cv)[idx + SEQ]  = h1;
                    ((bf16*)C2v)[idx]       = l0;
                    ((bf16*)C2v)[idx + SEQ] = l1;
                }
            }
}

// QKV batched: z selects input/weight/bias/output. Q gets alpha=SCL2 folded in.
__global__ void __launch_bounds__(256, 3)
gemm3_qkv(const bf16* __restrict__ qh, const bf16* __restrict__ ql,
          const bf16* __restrict__ kh, const bf16* __restrict__ kl,
          const bf16* __restrict__ vh, const bf16* __restrict__ vl,
          const bf16* __restrict__ wqh, const bf16* __restrict__ wql,
          const bf16* __restrict__ wkh, const bf16* __restrict__ wkl,
          const bf16* __restrict__ wvh, const bf16* __restrict__ wvl,
          const float* __restrict__ bq, const float* __restrict__ bk,
          const float* __restrict__ bv,
          bf16* Qh, bf16* Ql, bf16* Kh, bf16* Kl, bf16* Vh, bf16* Vl)
{
    const int z = blockIdx.z;
    const bf16* Ah = (z == 0) ? qh : (z == 1) ? kh : vh;
    const bf16* Al = (z == 0) ? ql : (z == 1) ? kl : vl;
    const bf16* Bh = (z == 0) ? wqh : (z == 1) ? wkh : wvh;
    const bf16* Bl = (z == 0) ? wql : (z == 1) ? wkl : wvl;
    const float* bias = (z == 0) ? bq : (z == 1) ? bk : bv;
    bf16* Ch  = (z == 0) ? Qh : (z == 1) ? Kh : Vh;
    bf16* C2h = (z == 0) ? Ql : (z == 1) ? Kl : Vl;
    gemm3_body(Ah, Al, Bh, Bl, bias, Ch, C2h, (z == 2) ? 2 : 1,
               (z == 0) ? SCL2 : 1.f);
}

__global__ void __launch_bounds__(256, 3)
gemm3_out(const bf16* __restrict__ Ah, const bf16* __restrict__ Al,
          const bf16* __restrict__ Bh, const bf16* __restrict__ Bl,
          const float* __restrict__ bias, float* Cv)
{
    gemm3_body(Ah, Al, Bh, Bl, bias, Cv, nullptr, 0, 1.f);
}

// ---------------------------------------------------------------------------
// Fused flash attention, 3xbf16, 64-key chunks, 3-stage ring, 1 sync/chunk.
// Q pre-scaled by SCL2 -> scores already in exp2 domain.
// ---------------------------------------------------------------------------
__global__ void __launch_bounds__(256, 2)
flash_attn(const bf16* __restrict__ Qh, const bf16* __restrict__ Ql,
           const bf16* __restrict__ Kh, const bf16* __restrict__ Kl,
           const bf16* __restrict__ Vh, const bf16* __restrict__ Vl,
           bf16* __restrict__ Oh, bf16* __restrict__ Ol)
{
    constexpr int KC = 64;
    constexpr int PADK = 72, PADV = 72;    // 144B rows: 16B-aligned, conflict-free
    constexpr int KSTG = KC * PADK, VSTG = 64 * PADV;
    constexpr int NCH = SEQ / KC;
    extern __shared__ bf16 sm[];
    bf16* sKh = sm;                        // [3][KSTG]
    bf16* sKl = sm + 3 * KSTG;
    bf16* sVh = sm + 6 * KSTG;             // [3][VSTG]
    bf16* sVl = sVh + 3 * VSTG;
    const uint32_t usm = (uint32_t)__cvta_generic_to_shared(sm);

    const int z = blockIdx.y;
    const bf16* pQh = Qh + (size_t)z * SEQ * DH;
    const bf16* pQl = Ql + (size_t)z * SEQ * DH;
    const bf16* pKh = Kh + (size_t)z * SEQ * DH;
    const bf16* pKl = Kl + (size_t)z * SEQ * DH;
    const bf16* pVh = Vh + (size_t)z * DH * SEQ;
    const bf16* pVl = Vl + (size_t)z * DH * SEQ;

    const int tid = threadIdx.x;
    const int lane = tid & 31, wid = tid >> 5;
    const int g = lane >> 2, tk = (lane & 3) * 2;
    const int r0 = blockIdx.x * 128 + wid * 16 + g;

    const int ld_row = ((lane >> 4) & 1) * 8 + (lane & 7);
    const int ld_col = ((lane >> 3) & 1) * 8;

    unsigned aQh[4][4], aQl[4][4];
#pragma unroll
    for (int kk = 0; kk < 4; kk++) {
        int kc = kk * 16 + tk;
        aQh[kk][0] = *(const unsigned*)&pQh[(size_t)r0 * DH + kc];
        aQh[kk][1] = *(const unsigned*)&pQh[(size_t)(r0 + 8) * DH + kc];
        aQh[kk][2] = *(const unsigned*)&pQh[(size_t)r0 * DH + kc + 8];
        aQh[kk][3] = *(const unsigned*)&pQh[(size_t)(r0 + 8) * DH + kc + 8];
        aQl[kk][0] = *(const unsigned*)&pQl[(size_t)r0 * DH + kc];
        aQl[kk][1] = *(const unsigned*)&pQl[(size_t)(r0 + 8) * DH + kc];
        aQl[kk][2] = *(const unsigned*)&pQl[(size_t)r0 * DH + kc + 8];
        aQl[kk][3] = *(const unsigned*)&pQl[(size_t)(r0 + 8) * DH + kc + 8];
    }

    auto stage_load = [&](int s, int kv0) {
#pragma unroll
        for (int c = tid; c < KC * 8; c += 256) {
            int row = c >> 3, qd = (c & 7) * 8;
            size_t go = (size_t)(kv0 + row) * DH + qd;
            int so = s * KSTG + row * PADK + qd;
            cpasync16(sKh + so, pKh + go);
            cpasync16(sKl + so, pKl + go);
        }
#pragma unroll
        for (int c = tid; c < 64 * 8; c += 256) {
            int d = c >> 3, qd = (c & 7) * 8;
            size_t go = (size_t)d * SEQ + kv0 + qd;
            int so = s * VSTG + d * PADV + qd;
            cpasync16(sVh + so, pVh + go);
            cpasync16(sVl + so, pVl + go);
        }
        cp_commit();
    };

    float m0 = -1e30f, m1 = -1e30f, l0 = 0.f, l1 = 0.f;
    float oacc[8][4];
#pragma unroll
    for (int dn = 0; dn < 8; dn++)
#pragma unroll
        for (int r = 0; r < 4; r++) oacc[dn][r] = 0.f;

    stage_load(0, 0);
    stage_load(1, KC);
    int scur = 0;

    for (int it = 0; it < NCH; it++) {
        if (it == NCH - 1) cp_wait<0>(); else cp_wait<1>();
        __syncthreads();                    // all warps done with slot being refilled
        if (it + 2 < NCH) {
            int snx = scur - 1; if (snx < 0) snx = 2;   // (it+2)%3
            stage_load(snx, (it + 2) * KC);
        }

        const uint32_t uKh = usm + 2u * (unsigned)(scur * KSTG);
        const uint32_t uKl = usm + 2u * (unsigned)(3 * KSTG + scur * KSTG);
        const uint32_t uVh = usm + 2u * (unsigned)(6 * KSTG + scur * VSTG);
        const uint32_t uVl = usm + 2u * (unsigned)(6 * KSTG + 3 * VSTG + scur * VSTG);

        // ---- S = Q @ K^T (exp2-scaled already) ----
        float sacc[8][4];
#pragma unroll
        for (int nj = 0; nj < 8; nj++) {
#pragma unroll
            for (int r = 0; r < 4; r++) sacc[nj][r] = 0.f;
        }
#pragma unroll
        for (int p = 0; p < 4; p++) {
            const uint32_t offK = 2u * (unsigned)((p * 16 + ld_row) * PADK + ld_col);
#pragma unroll
            for (int kk = 0; kk < 4; kk++) {
                unsigned bh4[4], bl4[4];
                ldm_x4(bh4, uKh + offK + 2u * (unsigned)(kk * 16));
                ldm_x4(bl4, uKl + offK + 2u * (unsigned)(kk * 16));
                mma16816(sacc[2 * p],     aQh[kk], bh4);
                mma16816(sacc[2 * p],     aQh[kk], bl4);
                mma16816(sacc[2 * p],     aQl[kk], bh4);
                mma16816(sacc[2 * p + 1], aQh[kk], bh4 + 2);
                mma16816(sacc[2 * p + 1], aQh[kk], bl4 + 2);
                mma16816(sacc[2 * p + 1], aQl[kk], bh4 + 2);
            }
        }

        // ---- online softmax (exp2 domain) ----
        float cm0 = -1e30f, cm1 = -1e30f;
#pragma unroll
        for (int nj = 0; nj < 8; nj++) {
            cm0 = fmaxf(cm0, fmaxf(sacc[nj][0], sacc[nj][1]));
            cm1 = fmaxf(cm1, fmaxf(sacc[nj][2], sacc[nj][3]));
        }
        cm0 = fmaxf(cm0, __shfl_xor_sync(0xffffffffu, cm0, 1));
        cm0 = fmaxf(cm0, __shfl_xor_sync(0xffffffffu, cm0, 2));
        cm1 = fmaxf(cm1, __shfl_xor_sync(0xffffffffu, cm1, 1));
        cm1 = fmaxf(cm1, __shfl_xor_sync(0xffffffffu, cm1, 2));
        float mn0 = fmaxf(m0, cm0), mn1 = fmaxf(m1, cm1);
        float f0 = ex2(m0 - mn0), f1 = ex2(m1 - mn1);
        m0 = mn0; m1 = mn1;

        float ps0 = 0.f, ps1 = 0.f;
#pragma unroll
        for (int nj = 0; nj < 8; nj++) {
            sacc[nj][0] = ex2(sacc[nj][0] - mn0);
            sacc[nj][1] = ex2(sacc[nj][1] - mn0);
            sacc[nj][2] = ex2(sacc[nj][2] - mn1);
            sacc[nj][3] = ex2(sacc[nj][3] - mn1);
            ps0 += sacc[nj][0] + sacc[nj][1];
            ps1 += sacc[nj][2] + sacc[nj][3];
        }
        ps0 += __shfl_xor_sync(0xffffffffu, ps0, 1);
        ps0 += __shfl_xor_sync(0xffffffffu, ps0, 2);
        ps1 += __shfl_xor_sync(0xffffffffu, ps1, 1);
        ps1 += __shfl_xor_sync(0xffffffffu, ps1, 2);
        l0 = l0 * f0 + ps0;
        l1 = l1 * f1 + ps1;

#pragma unroll
        for (int dn = 0; dn < 8; dn++) {
            oacc[dn][0] *= f0; oacc[dn][1] *= f0;
            oacc[dn][2] *= f1; oacc[dn][3] *= f1;
        }

        // ---- O += P @ V ----
#pragma unroll
        for (int kk = 0; kk < 4; kk++) {
            unsigned ah_[4], al_[4];
            const int t0 = 2 * kk, t1 = 2 * kk + 1;
            split2pack(sacc[t0][0], sacc[t0][1], ah_[0], al_[0]);
            split2pack(sacc[t0][2], sacc[t0][3], ah_[1], al_[1]);
            split2pack(sacc[t1][0], sacc[t1][1], ah_[2], al_[2]);
            split2pack(sacc[t1][2], sacc[t1][3], ah_[3], al_[3]);
#pragma unroll
            for (int dp = 0; dp < 4; dp++) {
                const uint32_t offV =
                    2u * (unsigned)((dp * 16 + ld_row) * PADV + kk * 16 + ld_col);
                unsigned vh4[4], vl4[4];
                ldm_x4(vh4, uVh + offV);
                ldm_x4(vl4, uVl + offV);
                mma16816(oacc[2 * dp],     ah_, vh4);
                mma16816(oacc[2 * dp],     ah_, vl4);
                mma16816(oacc[2 * dp],     al_, vh4);
                mma16816(oacc[2 * dp + 1], ah_, vh4 + 2);
                mma16816(oacc[2 * dp + 1], ah_, vl4 + 2);
                mma16816(oacc[2 * dp + 1], al_, vh4 + 2);
            }
        }

        scur = (scur == 2) ? 0 : scur + 1;
    }

    // ---- epilogue ----
    const float inv0 = 1.f / l0, inv1 = 1.f / l1;
    const int b = z >> 4, h = z & (HEADS - 1);
#pragma unroll
    for (int dn = 0; dn < 8; dn++) {
        const int c = h * DH + dn * 8 + tk;
        size_t i0 = ((size_t)(b * SEQ + r0)) * DMODEL + c;
        size_t i1 = ((size_t)(b * SEQ + r0 + 8)) * DMODEL + c;
        unsigned uh, ul;
        split2pack(oacc[dn][0] * inv0, oacc[dn][1] * inv0, uh, ul);
        *(unsigned*)(Oh + i0) = uh; *(unsigned*)(Ol + i0) = ul;
        split2pack(oacc[dn][2] * inv1, oacc[dn][3] * inv1, uh, ul);
        *(unsigned*)(Oh + i1) = uh; *(unsigned*)(Ol + i1) = ul;
    }
}

// ---------------------------------------------------------------------------
extern "C" void kernel_launch(void* const* d_in, const int* in_sizes, int n_in,
                              void* d_out, int out_size)
{
    const float* v  = (const float*)d_in[0];
    const float* k  = (const float*)d_in[1];
    const float* q  = (const float*)d_in[2];
    const float* wq = (const float*)d_in[3];
    const float* bq = (const float*)d_in[4];
    const float* wk = (const float*)d_in[5];
    const float* bk = (const float*)d_in[6];
    const float* wv = (const float*)d_in[7];
    const float* bv = (const float*)d_in[8];
    const float* wo = (const float*)d_in[9];
    const float* bo = (const float*)d_in[10];
    float* out = (float*)d_out;

    bf16 *q_hi, *q_lo, *k_hi, *k_lo, *v_hi, *v_lo;
    bf16 *wqT_hi, *wqT_lo, *wkT_hi, *wkT_lo, *wvT_hi, *wvT_lo, *woT_hi, *woT_lo;
    bf16 *Qh_hi, *Qh_lo, *Kh_hi, *Kh_lo, *VhT_hi, *VhT_lo, *Att_hi, *Att_lo;
    cudaGetSymbolAddress((void**)&q_hi,  g_q_hi);  cudaGetSymbolAddress((void**)&q_lo,  g_q_lo);
    cudaGetSymbolAddress((void**)&k_hi,  g_k_hi);  cudaGetSymbolAddress((void**)&k_lo,  g_k_lo);
    cudaGetSymbolAddress((void**)&v_hi,  g_v_hi);  cudaGetSymbolAddress((void**)&v_lo,  g_v_lo);
    cudaGetSymbolAddress((void**)&wqT_hi, g_wqT_hi); cudaGetSymbolAddress((void**)&wqT_lo, g_wqT_lo);
    cudaGetSymbolAddress((void**)&wkT_hi, g_wkT_hi); cudaGetSymbolAddress((void**)&wkT_lo, g_wkT_lo);
    cudaGetSymbolAddress((void**)&wvT_hi, g_wvT_hi); cudaGetSymbolAddress((void**)&wvT_lo, g_wvT_lo);
    cudaGetSymbolAddress((void**)&woT_hi, g_woT_hi); cudaGetSymbolAddress((void**)&woT_lo, g_woT_lo);
    cudaGetSymbolAddress((void**)&Qh_hi,  g_Qh_hi);  cudaGetSymbolAddress((void**)&Qh_lo,  g_Qh_lo);
    cudaGetSymbolAddress((void**)&Kh_hi,  g_Kh_hi);  cudaGetSymbolAddress((void**)&Kh_lo,  g_Kh_lo);
    cudaGetSymbolAddress((void**)&VhT_hi, g_VhT_hi); cudaGetSymbolAddress((void**)&VhT_lo, g_VhT_lo);
    cudaGetSymbolAddress((void**)&Att_hi, g_Att_hi); cudaGetSymbolAddress((void**)&Att_lo, g_Att_lo);

    const size_t smemGE = 65536;                                          // 64KB
    const size_t smemFA = (size_t)(12 * 64 * 72) * sizeof(bf16);          // 110592
    cudaFuncSetAttribute(gemm3_qkv, cudaFuncAttributeMaxDynamicSharedMemorySize, (int)smemGE);
    cudaFuncSetAttribute(gemm3_out, cudaFuncAttributeMaxDynamicSharedMemorySize, (int)smemGE);
    cudaFuncSetAttribute(flash_attn, cudaFuncAttributeMaxDynamicSharedMemorySize, (int)smemFA);

    // launch 0: all prep (input splits + weight transposes)
    {
        dim3 g(32, 32, 7), b(256);
        prep_k<<<g, b>>>(q, k, v, wq, wk, wv, wo,
                         q_hi, q_lo, k_hi, k_lo, v_hi, v_lo,
                         wqT_hi, wqT_lo, wkT_hi, wkT_lo,
                         wvT_hi, wvT_lo, woT_hi, woT_lo);
    }

    // launch 1: QKV projections (z-batched, 3 CTAs/SM target)
    {
        dim3 grid(DMODEL / 128, NROWS / 128, 3);
        gemm3_qkv<<<grid, 256, smemGE>>>(q_hi, q_lo, k_hi, k_lo, v_hi, v_lo,
                                         wqT_hi, wqT_lo, wkT_hi, wkT_lo, wvT_hi, wvT_lo,
                                         bq, bk, bv,
                                         Qh_hi, Qh_lo, Kh_hi, Kh_lo, VhT_hi, VhT_lo);
    }

    // launch 2: fused attention
    {
        dim3 grid(SEQ / 128, ZBH);
        flash_attn<<<grid, 256, smemFA>>>(Qh_hi, Qh_lo, Kh_hi, Kh_lo,
                                          VhT_hi, VhT_lo, Att_hi, Att_lo);
    }

    // launch 3: out = Att @ wo + bo
    {
        dim3 grid(DMODEL / 128, NROWS / 128);
        gemm3_out<<<grid, 256, smemGE>>>(Att_hi, Att_lo, woT_hi, woT_lo, bo, out);
    }
}